// round 4
// baseline (speedup 1.0000x reference)
#include <cuda_runtime.h>

// VectorQuantize: x[N=65536,256] f32, codebook[1024,256] f32
// Reference model: dot = cuBLAS sgemm (per-output single fp32 accumulator, FFMA, k ascending);
// c_sq = XLA warp row-reduce (lane-strided mul+add partials, shfl_down tree 16/8/4/2/1);
// dist = (x_sq - 2*dot) + c_sq fp32; argmin first-min; out = x + (q - x); loss = mean((x-q)^2).
// We replicate dot and c_sq rounding exactly; x_sq is common-mode (argmin-irrelevant).

#define DDIM    256
#define KCODES  1024
#define TM      64
#define THREADS 256
#define NMAX    65536

__device__ float g_csq[KCODES];
__device__ float g_tokloss[NMAX];

// smem layout (floats)
#define XS_STRIDE 260
#define CS_STRIDE 68
#define SM_XS     0
#define SM_CS     (SM_XS + TM * XS_STRIDE)
#define SM_RV     (SM_CS + 16 * CS_STRIDE)          // best val  64 x 17
#define SM_RI     (SM_RV + TM * 17)                 // best idx  64 x 17
#define SM_XSQ    (SM_RI + TM * 17)
#define SM_IDX    (SM_XSQ + TM)
#define SM_TOTAL  (SM_IDX + TM)
#define SMEM_BYTES (SM_TOTAL * 4)

// c_sq in XLA row-reduce order: one warp per row; lane partial over strided
// elements (lane, lane+32, ..., lane+224) with NON-contracted mul/add; then
// shfl_down tree 16,8,4,2,1.
__global__ void csq_kernel(const float* __restrict__ cb) {
    const int warp = (blockIdx.x * blockDim.x + threadIdx.x) >> 5;
    const int lane = threadIdx.x & 31;
    if (warp >= KCODES) return;
    const float* row = cb + (size_t)warp * DDIM;
    float p = 0.f;
#pragma unroll
    for (int i = 0; i < 8; i++) {
        float v = row[lane + i * 32];
        p = __fadd_rn(p, __fmul_rn(v, v));
    }
#pragma unroll
    for (int off = 16; off > 0; off >>= 1)
        p = __fadd_rn(p, __shfl_down_sync(0xffffffffu, p, off));
    if (lane == 0) g_csq[warp] = p;
}

__global__ void __launch_bounds__(THREADS) vq_main(
    const float* __restrict__ x, const float* __restrict__ cb,
    float* __restrict__ out, float* __restrict__ out_idx)
{
    extern __shared__ float sm[];
    float* x_s  = sm + SM_XS;
    float* c_s  = sm + SM_CS;
    float* rv   = sm + SM_RV;
    int*   ri   = (int*)(sm + SM_RI);
    float* xsq  = sm + SM_XSQ;
    int*   idxs = (int*)(sm + SM_IDX);

    const int tid = threadIdx.x;
    const int tx  = tid & 15;       // code group (4 codes)
    const int ty  = tid >> 4;       // token group (4 tokens)
    const size_t tokenBase = (size_t)blockIdx.x * TM;
    const float* xblk = x + tokenBase * DDIM;

    // stage x tile (64 x 256)
    {
        const float4* xg = reinterpret_cast<const float4*>(xblk);
#pragma unroll
        for (int it = 0; it < 16; it++) {
            int idx = it * THREADS + tid;
            int t  = idx >> 6;
            int c4 = idx & 63;
            *reinterpret_cast<float4*>(&x_s[t * XS_STRIDE + c4 * 4]) = xg[idx];
        }
    }
    __syncthreads();

    // x_sq per token (common-mode for argmin; any accurate order is fine)
    if (tid < TM) {
        const float* row = &x_s[tid * XS_STRIDE];
        float s = 0.f;
#pragma unroll 8
        for (int d = 0; d < DDIM; d++) s += row[d] * row[d];
        xsq[tid] = s;
    }
    // covered by first __syncthreads inside the chunk loop

    float best[4];
    int   bidx[4];
#pragma unroll
    for (int i = 0; i < 4; i++) { best[i] = 3.4e38f; bidx[i] = 0; }

    for (int kc = 0; kc < KCODES; kc += 64) {
        float acc[4][4];
#pragma unroll
        for (int i = 0; i < 4; i++)
#pragma unroll
            for (int j = 0; j < 4; j++) acc[i][j] = 0.f;

        float4 csq4 = *reinterpret_cast<const float4*>(&g_csq[kc + tx * 4]);

        for (int d0 = 0; d0 < DDIM; d0 += 16) {
            __syncthreads();
            {   // stage codebook chunk transposed: c_s[dd][code]
                int r  = tid >> 2;
                int cg = tid & 3;
                float4 v = *reinterpret_cast<const float4*>(
                    &cb[(size_t)(kc + r) * DDIM + d0 + cg * 4]);
                c_s[(cg * 4 + 0) * CS_STRIDE + r] = v.x;
                c_s[(cg * 4 + 1) * CS_STRIDE + r] = v.y;
                c_s[(cg * 4 + 2) * CS_STRIDE + r] = v.z;
                c_s[(cg * 4 + 3) * CS_STRIDE + r] = v.w;
            }
            __syncthreads();

            // dot accumulation: single fp32 accumulator per (token,code),
            // FFMA, k strictly ascending 0..255 -> matches cuBLAS sgemm rounding.
#pragma unroll
            for (int dd4 = 0; dd4 < 16; dd4 += 4) {
                float xr[4][4];
#pragma unroll
                for (int i = 0; i < 4; i++) {
                    float4 v = *reinterpret_cast<const float4*>(
                        &x_s[(ty * 4 + i) * XS_STRIDE + d0 + dd4]);
                    xr[i][0] = v.x; xr[i][1] = v.y; xr[i][2] = v.z; xr[i][3] = v.w;
                }
#pragma unroll
                for (int dd = 0; dd < 4; dd++) {
                    float4 cv = *reinterpret_cast<const float4*>(
                        &c_s[(dd4 + dd) * CS_STRIDE + tx * 4]);
#pragma unroll
                    for (int i = 0; i < 4; i++) {
                        float a = xr[i][dd];
                        acc[i][0] = __fmaf_rn(a, cv.x, acc[i][0]);
                        acc[i][1] = __fmaf_rn(a, cv.y, acc[i][1]);
                        acc[i][2] = __fmaf_rn(a, cv.z, acc[i][2]);
                        acc[i][3] = __fmaf_rn(a, cv.w, acc[i][3]);
                    }
                }
            }
        }

        float cs[4] = {csq4.x, csq4.y, csq4.z, csq4.w};
#pragma unroll
        for (int i = 0; i < 4; i++) {
            float xq = xsq[ty * 4 + i];
#pragma unroll
            for (int j = 0; j < 4; j++) {
                float dist = __fadd_rn(__fsub_rn(xq, __fmul_rn(2.0f, acc[i][j])), cs[j]);
                int k = kc + tx * 4 + j;
                if (dist < best[i]) { best[i] = dist; bidx[i] = k; }   // ascending k: first-min
            }
        }
    }

    // cross-thread argmin reduce (16 candidates per token), first-min tiebreak
    __syncthreads();
#pragma unroll
    for (int i = 0; i < 4; i++) {
        rv[(ty * 4 + i) * 17 + tx] = best[i];
        ri[(ty * 4 + i) * 17 + tx] = bidx[i];
    }
    __syncthreads();

    if (tid < TM) {
        float bv = rv[tid * 17]; int bi = ri[tid * 17];
#pragma unroll
        for (int t = 1; t < 16; t++) {
            float v = rv[tid * 17 + t];
            int  ix = ri[tid * 17 + t];
            if (v < bv || (v == bv && ix < bi)) { bv = v; bi = ix; }
        }
        idxs[tid] = bi;
        if (out_idx) out_idx[tokenBase + tid] = (float)bi;
    }
    __syncthreads();

    // output + per-token loss: warp handles 8 tokens, coalesced, deterministic
    {
        const int wid = tid >> 5, lane = tid & 31;
#pragma unroll
        for (int tt = 0; tt < 8; tt++) {
            int t = wid * 8 + tt;
            const float4* qrow = reinterpret_cast<const float4*>(cb + (size_t)idxs[t] * DDIM);
            float4*       orow = reinterpret_cast<float4*>(out + (tokenBase + t) * DDIM);
            float s = 0.f;
#pragma unroll
            for (int h = 0; h < 2; h++) {
                int i = h * 32 + lane;
                float4 xv = *reinterpret_cast<const float4*>(&x_s[t * XS_STRIDE + i * 4]);
                float4 q  = qrow[i];
                float4 o;
                o.x = xv.x + (q.x - xv.x);
                o.y = xv.y + (q.y - xv.y);
                o.z = xv.z + (q.z - xv.z);
                o.w = xv.w + (q.w - xv.w);
                orow[i] = o;
                float dx = xv.x - q.x, dy = xv.y - q.y, dz = xv.z - q.z, dw = xv.w - q.w;
                s += dx * dx + dy * dy + dz * dz + dw * dw;
            }
#pragma unroll
            for (int off = 16; off > 0; off >>= 1)
                s += __shfl_down_sync(0xffffffffu, s, off);
            if (lane == 0) g_tokloss[tokenBase + t] = s;
        }
    }
}

__global__ void loss_final(float* __restrict__ out_loss, float inv, int n) {
    __shared__ float red[1024];
    const int tid = threadIdx.x;
    float s = 0.f;
    for (int i = tid; i < n; i += 1024) s += g_tokloss[i];
    red[tid] = s;
    __syncthreads();
    for (int off = 512; off > 0; off >>= 1) {
        if (tid < off) red[tid] += red[tid + off];
        __syncthreads();
    }
    if (tid == 0) *out_loss = red[0] * inv;
}

extern "C" void kernel_launch(void* const* d_in, const int* in_sizes, int n_in,
                              void* d_out, int out_size)
{
    const float* x  = (const float*)d_in[0];
    const float* cb = (const float*)d_in[1];
    const long long n_elems = (long long)in_sizes[0];   // N * 256
    const int N = (int)(n_elems / DDIM);
    const int nblocks = N / TM;

    float* out   = (float*)d_out;
    float* oidx  = nullptr;
    float* oloss = nullptr;
    const long long need_idx = n_elems + N;
    if ((long long)out_size >= need_idx)      oidx  = out + n_elems;
    if ((long long)out_size >= need_idx + 1)  oloss = out + need_idx;
    else if ((long long)out_size == n_elems + 1) oloss = out + n_elems;

    cudaFuncSetAttribute(vq_main, cudaFuncAttributeMaxDynamicSharedMemorySize, SMEM_BYTES);

    csq_kernel<<<(KCODES * 32 + 255) / 256, 256>>>(cb);
    vq_main<<<nblocks, THREADS, SMEM_BYTES>>>(x, cb, out, oidx);
    if (oloss) loss_final<<<1, 1024>>>(oloss, 1.0f / ((float)N * (float)DDIM), N);
}

// round 6
// speedup vs baseline: 1.4599x; 1.4599x over previous
#include <cuda_runtime.h>
#include <cuda_bf16.h>
#include <cstdint>

// VectorQuantize, GB300 (sm_103 base PTX target: no tcgen05; use HMMA mma.sync).
// Pinned-exact fp32 recipe (R4, rel_err==0):
//   dot  = single fp32 accumulator, FFMA, d ascending
//   dist = __fadd_rn(__fsub_rn(xsq, __fmul_rn(2.f, dot)), csq)
//   csq  = XLA warp row-reduce; argmin = first-min
// Phase1: bf16 mma.sync GEMM -> approx dist = csq - 2*score; top-2 gap < 0.75
// flags token for exact rescue with the pinned recipe.

#define DDIM    256
#define KCODES  1024
#define NMAX    65536
#define RESCUE_THRESH 0.75f

__device__ float g_csq[KCODES];
__device__ float g_tokloss[NMAX];
__device__ int   g_bestidx[NMAX];
__device__ int   g_rescue_list[NMAX];
__device__ int   g_rescue_cnt;
__device__ __nv_bfloat16 g_xbf[NMAX * DDIM];
__device__ __nv_bfloat16 g_cbbf[KCODES * DDIM];

__device__ __forceinline__ uint32_t smem_u32(const void* p) {
    uint32_t a;
    asm("{ .reg .u64 t; cvta.to.shared.u64 t, %1; cvt.u32.u64 %0, t; }" : "=r"(a) : "l"(p));
    return a;
}
#define CP_ASYNC16(dst, src) \
    asm volatile("cp.async.cg.shared.global [%0], [%1], 16;" :: "r"(dst), "l"(src))
#define CP_COMMIT() asm volatile("cp.async.commit_group;" ::: "memory")
#define CP_WAIT0()  asm volatile("cp.async.wait_group 0;" ::: "memory")

__device__ __forceinline__ void ldmatrix_x4(uint32_t& r0, uint32_t& r1, uint32_t& r2,
                                            uint32_t& r3, uint32_t addr) {
    asm volatile("ldmatrix.sync.aligned.m8n8.x4.shared.b16 {%0,%1,%2,%3}, [%4];"
                 : "=r"(r0), "=r"(r1), "=r"(r2), "=r"(r3) : "r"(addr));
}
__device__ __forceinline__ void mma_bf16(float& c0, float& c1, float& c2, float& c3,
                                         uint32_t a0, uint32_t a1, uint32_t a2, uint32_t a3,
                                         uint32_t b0, uint32_t b1) {
    asm volatile("mma.sync.aligned.m16n8k16.row.col.f32.bf16.bf16.f32 "
                 "{%0,%1,%2,%3}, {%4,%5,%6,%7}, {%8,%9}, {%0,%1,%2,%3};"
                 : "+f"(c0), "+f"(c1), "+f"(c2), "+f"(c3)
                 : "r"(a0), "r"(a1), "r"(a2), "r"(a3), "r"(b0), "r"(b1));
}

// ---------------- setup kernels ----------------

__global__ void convert_kernel(const float* __restrict__ x, const float* __restrict__ cb,
                               int nx4) {
    if (blockIdx.x == 0 && threadIdx.x == 0) g_rescue_cnt = 0;
    const int gsz = gridDim.x * blockDim.x;
    const int gtid = blockIdx.x * blockDim.x + threadIdx.x;
    const float4* x4 = reinterpret_cast<const float4*>(x);
    for (int u = gtid; u < nx4; u += gsz) {
        float4 v = x4[u];
        ushort4 o;
        o.x = __bfloat16_as_ushort(__float2bfloat16(v.x));
        o.y = __bfloat16_as_ushort(__float2bfloat16(v.y));
        o.z = __bfloat16_as_ushort(__float2bfloat16(v.z));
        o.w = __bfloat16_as_ushort(__float2bfloat16(v.w));
        *reinterpret_cast<ushort4*>(g_xbf + (size_t)u * 4) = o;
    }
    const float4* c4 = reinterpret_cast<const float4*>(cb);
    for (int u = gtid; u < KCODES * DDIM / 4; u += gsz) {
        float4 v = c4[u];
        ushort4 o;
        o.x = __bfloat16_as_ushort(__float2bfloat16(v.x));
        o.y = __bfloat16_as_ushort(__float2bfloat16(v.y));
        o.z = __bfloat16_as_ushort(__float2bfloat16(v.z));
        o.w = __bfloat16_as_ushort(__float2bfloat16(v.w));
        *reinterpret_cast<ushort4*>(g_cbbf + (size_t)u * 4) = o;
    }
}

// c_sq, pinned R4 recipe (XLA warp row-reduce)
__global__ void csq_kernel(const float* __restrict__ cb) {
    const int warp = (blockIdx.x * blockDim.x + threadIdx.x) >> 5;
    const int lane = threadIdx.x & 31;
    if (warp >= KCODES) return;
    const float* row = cb + (size_t)warp * DDIM;
    float p = 0.f;
#pragma unroll
    for (int i = 0; i < 8; i++) {
        float v = row[lane + i * 32];
        p = __fadd_rn(p, __fmul_rn(v, v));
    }
#pragma unroll
    for (int off = 16; off > 0; off >>= 1)
        p = __fadd_rn(p, __shfl_down_sync(0xffffffffu, p, off));
    if (lane == 0) g_csq[warp] = p;
}

// ---------------- phase 1: bf16 HMMA filter ----------------
// smem: A 64KB | B0 64KB | B1 64KB | csq0 512B | csq1 512B
#define SA_OFF   0
#define SB_OFF   65536
#define SC_OFF   196608
#define SM_TOTAL 197632
// row stride 512B (256 bf16); 16B chunk index c (0..31) stored at (c ^ (row&7))

__global__ void __launch_bounds__(256) vq_phase1(void) {
    extern __shared__ char smem[];
    const uint32_t sb = smem_u32(smem);
    const int tid  = threadIdx.x;
    const int w    = tid >> 5;
    const int lane = tid & 31;
    const int tokenBase = blockIdx.x * 128;

    // issue A tile (128x256 bf16) + B chunk0 + csq0 via cp.async
    {
        const char* asrc = reinterpret_cast<const char*>(g_xbf + (size_t)tokenBase * DDIM);
        for (int u = tid; u < 4096; u += 256) {
            int row = u >> 5, c = u & 31;
            CP_ASYNC16(sb + SA_OFF + row * 512 + ((c ^ (row & 7)) << 4),
                       asrc + row * 512 + (c << 4));
        }
        const char* bsrc = reinterpret_cast<const char*>(g_cbbf);
        for (int u = tid; u < 4096; u += 256) {
            int row = u >> 5, c = u & 31;
            CP_ASYNC16(sb + SB_OFF + row * 512 + ((c ^ (row & 7)) << 4),
                       bsrc + row * 512 + (c << 4));
        }
        if (tid < 32)
            CP_ASYNC16(sb + SC_OFF + tid * 16,
                       reinterpret_cast<const char*>(g_csq) + tid * 16);
        CP_COMMIT();
        CP_WAIT0();
    }
    __syncthreads();

    // per-lane running argmin state: rows q=lane/4 (low) and q+8 (high)
    const int q  = lane >> 2;
    const int qi = lane & 3;
    float bL = 3.4e38f, sL = 3.4e38f, bH = 3.4e38f, sH = 3.4e38f;
    int   iL = 0, iH = 0;

    // A ldmatrix lane address components (fixed across ksteps)
    const int arow  = w * 16 + (lane & 15);
    const uint32_t abase = sb + SA_OFF + arow * 512;
    const int asw   = arow & 7;
    const int akoff = lane >> 4;          // 0: k0-7, 1: k8-15

    // B ldmatrix.x4 lane address components: 2 n-tiles per load
    //   lanes 0-7:  ntile nt,   kchunk lo;  8-15: nt,   hi
    //   lanes16-23: ntile nt+1, lo;        24-31: nt+1, hi
    const int l7    = lane & 7;
    const int bnsel = lane >> 4;          // 0 -> nt, 1 -> nt+1
    const int bkoff = (lane >> 3) & 1;
    const int bsw   = l7;

    for (int ch = 0; ch < 8; ch++) {
        const uint32_t Bcur = sb + SB_OFF + (ch & 1) * 65536;
        const float*   csqs = reinterpret_cast<const float*>(smem + SC_OFF + (ch & 1) * 512);

        // prefetch next B chunk + csq
        if (ch + 1 < 8) {
            const uint32_t Bnxt = sb + SB_OFF + ((ch + 1) & 1) * 65536;
            const char* bsrc = reinterpret_cast<const char*>(
                g_cbbf + (size_t)(ch + 1) * 128 * DDIM);
            for (int u = tid; u < 4096; u += 256) {
                int row = u >> 5, c = u & 31;
                CP_ASYNC16(Bnxt + row * 512 + ((c ^ (row & 7)) << 4),
                           bsrc + row * 512 + (c << 4));
            }
            if (tid < 32)
                CP_ASYNC16(sb + SC_OFF + ((ch + 1) & 1) * 512 + tid * 16,
                           reinterpret_cast<const char*>(g_csq + (ch + 1) * 128) + tid * 16);
            CP_COMMIT();
        }

        float acc[16][4];
#pragma unroll
        for (int nt = 0; nt < 16; nt++)
#pragma unroll
            for (int j = 0; j < 4; j++) acc[nt][j] = 0.f;

#pragma unroll
        for (int ks = 0; ks < 16; ks++) {
            uint32_t a0, a1, a2, a3;
            ldmatrix_x4(a0, a1, a2, a3,
                        abase + (((2 * ks + akoff) ^ asw) << 4));
#pragma unroll
            for (int nt = 0; nt < 16; nt += 2) {
                uint32_t b0, b1, b2, b3;
                int brow = (nt + bnsel) * 8 + l7;
                ldmatrix_x4(b0, b1, b2, b3,
                            Bcur + brow * 512 + (((2 * ks + bkoff) ^ bsw) << 4));
                mma_bf16(acc[nt][0], acc[nt][1], acc[nt][2], acc[nt][3],
                         a0, a1, a2, a3, b0, b1);
                mma_bf16(acc[nt + 1][0], acc[nt + 1][1], acc[nt + 1][2], acc[nt + 1][3],
                         a0, a1, a2, a3, b2, b3);
            }
        }

        // epilogue: dist = csq - 2*score; running top-2, codes ascending in-lane
#pragma unroll
        for (int nt = 0; nt < 16; nt++) {
            float2 cs = *reinterpret_cast<const float2*>(csqs + nt * 8 + 2 * qi);
            int code = ch * 128 + nt * 8 + 2 * qi;
            float d0 = __fmaf_rn(-2.0f, acc[nt][0], cs.x);
            float d1 = __fmaf_rn(-2.0f, acc[nt][1], cs.y);
            float d2 = __fmaf_rn(-2.0f, acc[nt][2], cs.x);
            float d3 = __fmaf_rn(-2.0f, acc[nt][3], cs.y);
            if (d0 < bL) { sL = bL; bL = d0; iL = code; } else if (d0 < sL) sL = d0;
            if (d1 < bL) { sL = bL; bL = d1; iL = code + 1; } else if (d1 < sL) sL = d1;
            if (d2 < bH) { sH = bH; bH = d2; iH = code; } else if (d2 < sH) sH = d2;
            if (d3 < bH) { sH = bH; bH = d3; iH = code + 1; } else if (d3 < sH) sH = d3;
        }

        CP_WAIT0();
        __syncthreads();
    }

    // quad merge (lanes 4q..4q+3) of (best, idx, second)
#pragma unroll
    for (int m = 1; m <= 2; m <<= 1) {
        float ob = __shfl_xor_sync(0xffffffffu, bL, m);
        float os = __shfl_xor_sync(0xffffffffu, sL, m);
        int   oi = __shfl_xor_sync(0xffffffffu, iL, m);
        if (ob < bL || (ob == bL && oi < iL)) { sL = fminf(bL, os); bL = ob; iL = oi; }
        else { sL = fminf(sL, ob); }
        ob = __shfl_xor_sync(0xffffffffu, bH, m);
        os = __shfl_xor_sync(0xffffffffu, sH, m);
        oi = __shfl_xor_sync(0xffffffffu, iH, m);
        if (ob < bH || (ob == bH && oi < iH)) { sH = fminf(bH, os); bH = ob; iH = oi; }
        else { sH = fminf(sH, ob); }
    }

    if (qi == 0) {
        int tL = tokenBase + w * 16 + q;
        int tH = tL + 8;
        g_bestidx[tL] = iL;
        g_bestidx[tH] = iH;
        if (sL - bL < RESCUE_THRESH) {
            int p = atomicAdd(&g_rescue_cnt, 1);
            if (p < NMAX) g_rescue_list[p] = tL;
        }
        if (sH - bH < RESCUE_THRESH) {
            int p = atomicAdd(&g_rescue_cnt, 1);
            if (p < NMAX) g_rescue_list[p] = tH;
        }
    }
}

// ---------------- exact rescue (pinned R4 arithmetic) ----------------
__global__ void __launch_bounds__(256) rescue_kernel(
    const float* __restrict__ x, const float* __restrict__ cb)
{
    __shared__ float xs[8][260];
    __shared__ float xq[8];
    __shared__ int   stok[8];
    __shared__ float rbv[8][256];
    __shared__ int   rbi[8][256];

    const int tid = threadIdx.x;
    int cnt = g_rescue_cnt;
    if (cnt > NMAX) cnt = NMAX;

    for (int base = blockIdx.x * 8; base < cnt; base += gridDim.x * 8) {
        int nt = cnt - base; if (nt > 8) nt = 8;
        __syncthreads();
        if (tid < nt) stok[tid] = g_rescue_list[base + tid];
        __syncthreads();
        for (int i = tid; i < nt * DDIM; i += 256) {
            int t = i >> 8, d = i & 255;
            xs[t][d] = x[(size_t)stok[t] * DDIM + d];
        }
        __syncthreads();
        if (tid < nt) {   // xsq: same source text as R4's vq_main
            const float* row = xs[tid];
            float s = 0.f;
#pragma unroll 8
            for (int d = 0; d < DDIM; d++) s += row[d] * row[d];
            xq[tid] = s;
        }
        __syncthreads();

        float bv[8]; int bi[8];
#pragma unroll
        for (int t = 0; t < 8; t++) { bv[t] = 3.4e38f; bi[t] = 0; }

#pragma unroll
        for (int j = 0; j < 4; j++) {
            int k = tid * 4 + j;
            const float* crow = cb + (size_t)k * DDIM;
            float acc[8];
#pragma unroll
            for (int t = 0; t < 8; t++) acc[t] = 0.f;
            for (int d = 0; d < DDIM; d++) {
                float c = __ldg(crow + d);
#pragma unroll
                for (int t = 0; t < 8; t++) acc[t] = __fmaf_rn(xs[t][d], c, acc[t]);
            }
            float csq = g_csq[k];
#pragma unroll
            for (int t = 0; t < 8; t++) {
                float dist = __fadd_rn(__fsub_rn(xq[t], __fmul_rn(2.0f, acc[t])), csq);
                if (dist < bv[t]) { bv[t] = dist; bi[t] = k; }
            }
        }
#pragma unroll
        for (int t = 0; t < 8; t++) { rbv[t][tid] = bv[t]; rbi[t][tid] = bi[t]; }
        __syncthreads();
        if (tid < nt) {
            float b = rbv[tid][0]; int bk = rbi[tid][0];
            for (int u = 1; u < 256; u++) {
                float v = rbv[tid][u]; int ii = rbi[tid][u];
                if (v < b || (v == b && ii < bk)) { b = v; bk = ii; }
            }
            g_bestidx[stok[tid]] = bk;
        }
    }
}

// ---------------- gather + STE + loss ----------------
__global__ void __launch_bounds__(256) gather_kernel(
    const float* __restrict__ x, const float* __restrict__ cb,
    float* __restrict__ out, float* __restrict__ oidx)
{
    const int token = (blockIdx.x * 256 + threadIdx.x) >> 5;
    const int lane = threadIdx.x & 31;
    const int k = g_bestidx[token];
    if (lane == 0 && oidx) oidx[token] = (float)k;
    const float4* xr = reinterpret_cast<const float4*>(x + (size_t)token * DDIM);
    const float4* qr = reinterpret_cast<const float4*>(cb + (size_t)k * DDIM);
    float4* orow = reinterpret_cast<float4*>(out + (size_t)token * DDIM);
    float s = 0.f;
#pragma unroll
    for (int h = 0; h < 2; h++) {
        int i = h * 32 + lane;
        float4 xv = xr[i], qv = qr[i];
        float4 o;
        o.x = xv.x + (qv.x - xv.x);
        o.y = xv.y + (qv.y - xv.y);
        o.z = xv.z + (qv.z - xv.z);
        o.w = xv.w + (qv.w - xv.w);
        orow[i] = o;
        float dx = xv.x - qv.x, dy = xv.y - qv.y, dz = xv.z - qv.z, dw = xv.w - qv.w;
        s += dx * dx + dy * dy + dz * dz + dw * dw;
    }
#pragma unroll
    for (int off = 16; off > 0; off >>= 1)
        s += __shfl_down_sync(0xffffffffu, s, off);
    if (lane == 0) g_tokloss[token] = s;
}

__global__ void loss_final(float* __restrict__ out_loss, float inv, int n) {
    __shared__ float red[1024];
    const int tid = threadIdx.x;
    float s = 0.f;
    for (int i = tid; i < n; i += 1024) s += g_tokloss[i];
    red[tid] = s;
    __syncthreads();
    for (int off = 512; off > 0; off >>= 1) {
        if (tid < off) red[tid] += red[tid + off];
        __syncthreads();
    }
    if (tid == 0) *out_loss = red[0] * inv;
}

extern "C" void kernel_launch(void* const* d_in, const int* in_sizes, int n_in,
                              void* d_out, int out_size)
{
    const float* x  = (const float*)d_in[0];
    const float* cb = (const float*)d_in[1];
    const long long n_elems = (long long)in_sizes[0];   // N * 256
    const int N = (int)(n_elems / DDIM);

    float* out   = (float*)d_out;
    float* oidx  = nullptr;
    float* oloss = nullptr;
    const long long need_idx = n_elems + N;
    if ((long long)out_size >= need_idx)      oidx  = out + n_elems;
    if ((long long)out_size >= need_idx + 1)  oloss = out + need_idx;
    else if ((long long)out_size == n_elems + 1) oloss = out + n_elems;

    cudaFuncSetAttribute(vq_phase1, cudaFuncAttributeMaxDynamicSharedMemorySize, SM_TOTAL);

    convert_kernel<<<1024, 256>>>(x, cb, (int)(n_elems / 4));
    csq_kernel<<<(KCODES * 32 + 255) / 256, 256>>>(cb);
    vq_phase1<<<N / 128, 256, SM_TOTAL>>>();
    rescue_kernel<<<296, 256>>>(x, cb);
    gather_kernel<<<N / 8, 256>>>(x, cb, out, oidx);
    if (oloss) loss_final<<<1, 1024>>>(oloss, 1.0f / ((float)N * (float)DDIM), N);
}

// round 7
// speedup vs baseline: 4.7983x; 3.2867x over previous
#include <cuda_runtime.h>
#include <cuda_bf16.h>
#include <cstdint>

// VectorQuantize, GB300 (sm_103 base PTX: HMMA mma.sync path).
// Pinned-exact fp32 recipe (R4, rel_err==0):
//   dot  = single fp32 accumulator, FFMA, d ascending
//   dist = __fadd_rn(__fsub_rn(xsq, __fmul_rn(2.f, dot)), csq)
//   csq  = XLA warp row-reduce; argmin = first-min
// Phase1: bf16 mma.sync filter; gap < 0.75 -> exact rescue (FMA-bound, cbT-coalesced).

#define DDIM    256
#define KCODES  1024
#define NMAX    65536
#define RESCUE_THRESH 0.75f
#define RT      16        // tokens per rescue block-iteration

__device__ float g_csq[KCODES];
__device__ float g_cbT[DDIM * KCODES];   // [d][k] transposed codebook (exact fp32 values)
__device__ float g_tokloss[NMAX];
__device__ int   g_bestidx[NMAX];
__device__ int   g_rescue_list[NMAX];
__device__ int   g_rescue_cnt;
__device__ __nv_bfloat16 g_xbf[NMAX * DDIM];
__device__ __nv_bfloat16 g_cbbf[KCODES * DDIM];

__device__ __forceinline__ uint32_t smem_u32(const void* p) {
    uint32_t a;
    asm("{ .reg .u64 t; cvta.to.shared.u64 t, %1; cvt.u32.u64 %0, t; }" : "=r"(a) : "l"(p));
    return a;
}
#define CP_ASYNC16(dst, src) \
    asm volatile("cp.async.cg.shared.global [%0], [%1], 16;" :: "r"(dst), "l"(src))
#define CP_COMMIT() asm volatile("cp.async.commit_group;" ::: "memory")
#define CP_WAIT0()  asm volatile("cp.async.wait_group 0;" ::: "memory")

__device__ __forceinline__ void ldmatrix_x4(uint32_t& r0, uint32_t& r1, uint32_t& r2,
                                            uint32_t& r3, uint32_t addr) {
    asm volatile("ldmatrix.sync.aligned.m8n8.x4.shared.b16 {%0,%1,%2,%3}, [%4];"
                 : "=r"(r0), "=r"(r1), "=r"(r2), "=r"(r3) : "r"(addr));
}
__device__ __forceinline__ void mma_bf16(float& c0, float& c1, float& c2, float& c3,
                                         uint32_t a0, uint32_t a1, uint32_t a2, uint32_t a3,
                                         uint32_t b0, uint32_t b1) {
    asm volatile("mma.sync.aligned.m16n8k16.row.col.f32.bf16.bf16.f32 "
                 "{%0,%1,%2,%3}, {%4,%5,%6,%7}, {%8,%9}, {%0,%1,%2,%3};"
                 : "+f"(c0), "+f"(c1), "+f"(c2), "+f"(c3)
                 : "r"(a0), "r"(a1), "r"(a2), "r"(a3), "r"(b0), "r"(b1));
}

// ---------------- setup kernels ----------------

__global__ void convert_kernel(const float* __restrict__ x, const float* __restrict__ cb,
                               int nx4) {
    if (blockIdx.x == 0 && threadIdx.x == 0) g_rescue_cnt = 0;
    const int gsz = gridDim.x * blockDim.x;
    const int gtid = blockIdx.x * blockDim.x + threadIdx.x;
    const float4* x4 = reinterpret_cast<const float4*>(x);
    for (int u = gtid; u < nx4; u += gsz) {
        float4 v = x4[u];
        ushort4 o;
        o.x = __bfloat16_as_ushort(__float2bfloat16(v.x));
        o.y = __bfloat16_as_ushort(__float2bfloat16(v.y));
        o.z = __bfloat16_as_ushort(__float2bfloat16(v.z));
        o.w = __bfloat16_as_ushort(__float2bfloat16(v.w));
        *reinterpret_cast<ushort4*>(g_xbf + (size_t)u * 4) = o;
    }
    const float4* c4 = reinterpret_cast<const float4*>(cb);
    for (int u = gtid; u < KCODES * DDIM / 4; u += gsz) {
        float4 v = c4[u];
        ushort4 o;
        o.x = __bfloat16_as_ushort(__float2bfloat16(v.x));
        o.y = __bfloat16_as_ushort(__float2bfloat16(v.y));
        o.z = __bfloat16_as_ushort(__float2bfloat16(v.z));
        o.w = __bfloat16_as_ushort(__float2bfloat16(v.w));
        *reinterpret_cast<ushort4*>(g_cbbf + (size_t)u * 4) = o;
    }
}

// c_sq (pinned R4 XLA warp row-reduce) + codebook transpose g_cbT[d][k]
__global__ void csq_kernel(const float* __restrict__ cb) {
    const int warp = (blockIdx.x * blockDim.x + threadIdx.x) >> 5;
    const int lane = threadIdx.x & 31;
    if (warp >= KCODES) return;
    const float* row = cb + (size_t)warp * DDIM;
    float p = 0.f;
#pragma unroll
    for (int i = 0; i < 8; i++) {
        float v = row[lane + i * 32];
        g_cbT[(size_t)(lane + i * 32) * KCODES + warp] = v;
        p = __fadd_rn(p, __fmul_rn(v, v));
    }
#pragma unroll
    for (int off = 16; off > 0; off >>= 1)
        p = __fadd_rn(p, __shfl_down_sync(0xffffffffu, p, off));
    if (lane == 0) g_csq[warp] = p;
}

// ---------------- phase 1: bf16 HMMA filter (unchanged from R6, passed) ----------------
#define SA_OFF   0
#define SB_OFF   65536
#define SC_OFF   196608
#define SM_TOTAL 197632

__global__ void __launch_bounds__(256) vq_phase1(void) {
    extern __shared__ char smem[];
    const uint32_t sb = smem_u32(smem);
    const int tid  = threadIdx.x;
    const int w    = tid >> 5;
    const int lane = tid & 31;
    const int tokenBase = blockIdx.x * 128;

    {
        const char* asrc = reinterpret_cast<const char*>(g_xbf + (size_t)tokenBase * DDIM);
        for (int u = tid; u < 4096; u += 256) {
            int row = u >> 5, c = u & 31;
            CP_ASYNC16(sb + SA_OFF + row * 512 + ((c ^ (row & 7)) << 4),
                       asrc + row * 512 + (c << 4));
        }
        const char* bsrc = reinterpret_cast<const char*>(g_cbbf);
        for (int u = tid; u < 4096; u += 256) {
            int row = u >> 5, c = u & 31;
            CP_ASYNC16(sb + SB_OFF + row * 512 + ((c ^ (row & 7)) << 4),
                       bsrc + row * 512 + (c << 4));
        }
        if (tid < 32)
            CP_ASYNC16(sb + SC_OFF + tid * 16,
                       reinterpret_cast<const char*>(g_csq) + tid * 16);
        CP_COMMIT();
        CP_WAIT0();
    }
    __syncthreads();

    const int q  = lane >> 2;
    const int qi = lane & 3;
    float bL = 3.4e38f, sL = 3.4e38f, bH = 3.4e38f, sH = 3.4e38f;
    int   iL = 0, iH = 0;

    const int arow  = w * 16 + (lane & 15);
    const uint32_t abase = sb + SA_OFF + arow * 512;
    const int asw   = arow & 7;
    const int akoff = lane >> 4;

    const int l7    = lane & 7;
    const int bnsel = lane >> 4;
    const int bkoff = (lane >> 3) & 1;
    const int bsw   = l7;

    for (int ch = 0; ch < 8; ch++) {
        const uint32_t Bcur = sb + SB_OFF + (ch & 1) * 65536;
        const float*   csqs = reinterpret_cast<const float*>(smem + SC_OFF + (ch & 1) * 512);

        if (ch + 1 < 8) {
            const uint32_t Bnxt = sb + SB_OFF + ((ch + 1) & 1) * 65536;
            const char* bsrc = reinterpret_cast<const char*>(
                g_cbbf + (size_t)(ch + 1) * 128 * DDIM);
            for (int u = tid; u < 4096; u += 256) {
                int row = u >> 5, c = u & 31;
                CP_ASYNC16(Bnxt + row * 512 + ((c ^ (row & 7)) << 4),
                           bsrc + row * 512 + (c << 4));
            }
            if (tid < 32)
                CP_ASYNC16(sb + SC_OFF + ((ch + 1) & 1) * 512 + tid * 16,
                           reinterpret_cast<const char*>(g_csq + (ch + 1) * 128) + tid * 16);
            CP_COMMIT();
        }

        float acc[16][4];
#pragma unroll
        for (int nt = 0; nt < 16; nt++)
#pragma unroll
            for (int j = 0; j < 4; j++) acc[nt][j] = 0.f;

#pragma unroll
        for (int ks = 0; ks < 16; ks++) {
            uint32_t a0, a1, a2, a3;
            ldmatrix_x4(a0, a1, a2, a3,
                        abase + (((2 * ks + akoff) ^ asw) << 4));
#pragma unroll
            for (int nt = 0; nt < 16; nt += 2) {
                uint32_t b0, b1, b2, b3;
                int brow = (nt + bnsel) * 8 + l7;
                ldmatrix_x4(b0, b1, b2, b3,
                            Bcur + brow * 512 + (((2 * ks + bkoff) ^ bsw) << 4));
                mma_bf16(acc[nt][0], acc[nt][1], acc[nt][2], acc[nt][3],
                         a0, a1, a2, a3, b0, b1);
                mma_bf16(acc[nt + 1][0], acc[nt + 1][1], acc[nt + 1][2], acc[nt + 1][3],
                         a0, a1, a2, a3, b2, b3);
            }
        }

#pragma unroll
        for (int nt = 0; nt < 16; nt++) {
            float2 cs = *reinterpret_cast<const float2*>(csqs + nt * 8 + 2 * qi);
            int code = ch * 128 + nt * 8 + 2 * qi;
            float d0 = __fmaf_rn(-2.0f, acc[nt][0], cs.x);
            float d1 = __fmaf_rn(-2.0f, acc[nt][1], cs.y);
            float d2 = __fmaf_rn(-2.0f, acc[nt][2], cs.x);
            float d3 = __fmaf_rn(-2.0f, acc[nt][3], cs.y);
            if (d0 < bL) { sL = bL; bL = d0; iL = code; } else if (d0 < sL) sL = d0;
            if (d1 < bL) { sL = bL; bL = d1; iL = code + 1; } else if (d1 < sL) sL = d1;
            if (d2 < bH) { sH = bH; bH = d2; iH = code; } else if (d2 < sH) sH = d2;
            if (d3 < bH) { sH = bH; bH = d3; iH = code + 1; } else if (d3 < sH) sH = d3;
        }

        CP_WAIT0();
        __syncthreads();
    }

#pragma unroll
    for (int m = 1; m <= 2; m <<= 1) {
        float ob = __shfl_xor_sync(0xffffffffu, bL, m);
        float os = __shfl_xor_sync(0xffffffffu, sL, m);
        int   oi = __shfl_xor_sync(0xffffffffu, iL, m);
        if (ob < bL || (ob == bL && oi < iL)) { sL = fminf(bL, os); bL = ob; iL = oi; }
        else { sL = fminf(sL, ob); }
        ob = __shfl_xor_sync(0xffffffffu, bH, m);
        os = __shfl_xor_sync(0xffffffffu, sH, m);
        oi = __shfl_xor_sync(0xffffffffu, iH, m);
        if (ob < bH || (ob == bH && oi < iH)) { sH = fminf(bH, os); bH = ob; iH = oi; }
        else { sH = fminf(sH, ob); }
    }

    if (qi == 0) {
        int tL = tokenBase + w * 16 + q;
        int tH = tL + 8;
        g_bestidx[tL] = iL;
        g_bestidx[tH] = iH;
        if (sL - bL < RESCUE_THRESH) {
            int p = atomicAdd(&g_rescue_cnt, 1);
            if (p < NMAX) g_rescue_list[p] = tL;
        }
        if (sH - bH < RESCUE_THRESH) {
            int p = atomicAdd(&g_rescue_cnt, 1);
            if (p < NMAX) g_rescue_list[p] = tH;
        }
    }
}

// ---------------- exact rescue v2: FMA-bound, cbT-coalesced ----------------
// block = 256 threads; per iter: RT tokens x 1024 codes; thread = 4 codes x RT tokens.
// Per d: 1 LDG.128 (cbT[d][4*tid]) + RT broadcast LDS + 4*RT FFMA.
__global__ void __launch_bounds__(256) rescue_kernel(const float* __restrict__ x)
{
    __shared__ float xs[RT][260];
    __shared__ float xq[RT];
    __shared__ int   stok[RT];
    __shared__ float rbv[RT][257];
    __shared__ int   rbi[RT][257];

    const int tid = threadIdx.x;
    int cnt = g_rescue_cnt;
    if (cnt > NMAX) cnt = NMAX;

    const float4 csqv = *reinterpret_cast<const float4*>(g_csq + tid * 4);

    for (int base = blockIdx.x * RT; base < cnt; base += gridDim.x * RT) {
        int nt = cnt - base; if (nt > RT) nt = RT;
        __syncthreads();
        if (tid < nt) stok[tid] = g_rescue_list[base + tid];
        __syncthreads();
        for (int i = tid; i < nt * DDIM; i += 256) {
            int t = i >> 8, d = i & 255;
            xs[t][d] = x[(size_t)stok[t] * DDIM + d];
        }
        __syncthreads();
        if (tid < nt) {   // pinned xsq (same source text as R4)
            const float* row = xs[tid];
            float s = 0.f;
#pragma unroll 8
            for (int d = 0; d < DDIM; d++) s += row[d] * row[d];
            xq[tid] = s;
        }
        __syncthreads();

        float a0[RT], a1[RT], a2[RT], a3[RT];
#pragma unroll
        for (int t = 0; t < RT; t++) { a0[t] = 0.f; a1[t] = 0.f; a2[t] = 0.f; a3[t] = 0.f; }

        const float4* ct = reinterpret_cast<const float4*>(g_cbT) + tid;
#pragma unroll 2
        for (int d = 0; d < DDIM; d++) {
            float4 c = ct[d * (KCODES / 4)];
#pragma unroll
            for (int t = 0; t < RT; t++) {
                float xv = xs[t][d];
                a0[t] = __fmaf_rn(xv, c.x, a0[t]);
                a1[t] = __fmaf_rn(xv, c.y, a1[t]);
                a2[t] = __fmaf_rn(xv, c.z, a2[t]);
                a3[t] = __fmaf_rn(xv, c.w, a3[t]);
            }
        }

        // pinned dist + per-thread first-min over its 4 ascending codes
#pragma unroll
        for (int t = 0; t < RT; t++) {
            float q = xq[t];
            float d0 = __fadd_rn(__fsub_rn(q, __fmul_rn(2.0f, a0[t])), csqv.x);
            float d1 = __fadd_rn(__fsub_rn(q, __fmul_rn(2.0f, a1[t])), csqv.y);
            float d2 = __fadd_rn(__fsub_rn(q, __fmul_rn(2.0f, a2[t])), csqv.z);
            float d3 = __fadd_rn(__fsub_rn(q, __fmul_rn(2.0f, a3[t])), csqv.w);
            float bv = d0; int bi = tid * 4;
            if (d1 < bv) { bv = d1; bi = tid * 4 + 1; }
            if (d2 < bv) { bv = d2; bi = tid * 4 + 2; }
            if (d3 < bv) { bv = d3; bi = tid * 4 + 3; }
            rbv[t][tid] = bv; rbi[t][tid] = bi;
        }
        __syncthreads();
        if (tid < nt) {   // threads ascending = codes ascending -> first-min
            float b = rbv[tid][0]; int bk = rbi[tid][0];
            for (int u = 1; u < 256; u++) {
                float v = rbv[tid][u]; int ii = rbi[tid][u];
                if (v < b || (v == b && ii < bk)) { b = v; bk = ii; }
            }
            g_bestidx[stok[tid]] = bk;
        }
    }
}

// ---------------- gather + STE + loss ----------------
__global__ void __launch_bounds__(256) gather_kernel(
    const float* __restrict__ x, const float* __restrict__ cb,
    float* __restrict__ out, float* __restrict__ oidx)
{
    const int token = (blockIdx.x * 256 + threadIdx.x) >> 5;
    const int lane = threadIdx.x & 31;
    const int k = g_bestidx[token];
    if (lane == 0 && oidx) oidx[token] = (float)k;
    const float4* xr = reinterpret_cast<const float4*>(x + (size_t)token * DDIM);
    const float4* qr = reinterpret_cast<const float4*>(cb + (size_t)k * DDIM);
    float4* orow = reinterpret_cast<float4*>(out + (size_t)token * DDIM);
    float s = 0.f;
#pragma unroll
    for (int h = 0; h < 2; h++) {
        int i = h * 32 + lane;
        float4 xv = xr[i], qv = qr[i];
        float4 o;
        o.x = xv.x + (qv.x - xv.x);
        o.y = xv.y + (qv.y - xv.y);
        o.z = xv.z + (qv.z - xv.z);
        o.w = xv.w + (qv.w - xv.w);
        orow[i] = o;
        float dx = xv.x - qv.x, dy = xv.y - qv.y, dz = xv.z - qv.z, dw = xv.w - qv.w;
        s += dx * dx + dy * dy + dz * dz + dw * dw;
    }
#pragma unroll
    for (int off = 16; off > 0; off >>= 1)
        s += __shfl_down_sync(0xffffffffu, s, off);
    if (lane == 0) g_tokloss[token] = s;
}

__global__ void loss_final(float* __restrict__ out_loss, float inv, int n) {
    __shared__ float red[1024];
    const int tid = threadIdx.x;
    float s = 0.f;
    for (int i = tid; i < n; i += 1024) s += g_tokloss[i];
    red[tid] = s;
    __syncthreads();
    for (int off = 512; off > 0; off >>= 1) {
        if (tid < off) red[tid] += red[tid + off];
        __syncthreads();
    }
    if (tid == 0) *out_loss = red[0] * inv;
}

extern "C" void kernel_launch(void* const* d_in, const int* in_sizes, int n_in,
                              void* d_out, int out_size)
{
    const float* x  = (const float*)d_in[0];
    const float* cb = (const float*)d_in[1];
    const long long n_elems = (long long)in_sizes[0];   // N * 256
    const int N = (int)(n_elems / DDIM);

    float* out   = (float*)d_out;
    float* oidx  = nullptr;
    float* oloss = nullptr;
    const long long need_idx = n_elems + N;
    if ((long long)out_size >= need_idx)      oidx  = out + n_elems;
    if ((long long)out_size >= need_idx + 1)  oloss = out + need_idx;
    else if ((long long)out_size == n_elems + 1) oloss = out + n_elems;

    cudaFuncSetAttribute(vq_phase1, cudaFuncAttributeMaxDynamicSharedMemorySize, SM_TOTAL);

    convert_kernel<<<1024, 256>>>(x, cb, (int)(n_elems / 4));
    csq_kernel<<<(KCODES * 32 + 255) / 256, 256>>>(cb);
    vq_phase1<<<N / 128, 256, SM_TOTAL>>>();
    rescue_kernel<<<592, 256>>>(x);
    gather_kernel<<<N / 8, 256>>>(x, cb, out, oidx);
    if (oloss) loss_final<<<1, 1024>>>(oloss, 1.0f / ((float)N * (float)DDIM), N);
}